// round 15
// baseline (speedup 1.0000x reference)
#include <cuda_runtime.h>
#include <cuda_bf16.h>
#include <cstdint>

typedef unsigned int uint;

// ---------------- problem constants ----------------
#define Bn   64
#define Tn   256
#define En   128
#define H1   256
#define H2   256
#define U3n  512
#define U4n  5000
#define ROWS (Bn*Tn)      // 16384

// ---------------- scratch ----------------
__device__ __nv_bfloat16 g_Z1cat[ROWS * 2048];    // bf16 (fw 0..1023, bw 1024..2047)
__device__ __nv_bfloat16 g_Z2 [ROWS * 1024];      // bf16
__device__ __nv_bfloat16 g_HS[ROWS * 512];
__device__ float g_HL [Bn * H2];
__device__ __nv_bfloat16 g_D3bf[Bn * U3n];
__device__ __nv_bfloat16 g_Xbf[ROWS * En];
__device__ __nv_bfloat16 g_W1cat[En * 2048];
__device__ float g_bcat[2048];
__device__ __nv_bfloat16 g_W2_bf [512 * 1024];
__device__ __nv_bfloat16 g_W4_bf [512 * U4n];
__device__ uint2 g_Upk[3 * 65536];                // packed U frags: U1f, U1b, U2m

// ---------------- helpers ----------------
__device__ __forceinline__ unsigned ctarank() {
    unsigned r; asm("mov.u32 %0, %%cluster_ctarank;" : "=r"(r)); return r;
}
__device__ __forceinline__ void cluster_sync_all() {
    asm volatile("barrier.cluster.arrive.aligned;\n\tbarrier.cluster.wait.aligned;" ::: "memory");
}
__device__ __forceinline__ unsigned mapa_addr(unsigned a, unsigned rank) {
    unsigned ra;
    asm volatile("mapa.shared::cluster.u32 %0, %1, %2;" : "=r"(ra) : "r"(a), "r"(rank));
    return ra;
}
__device__ __forceinline__ void bulk_s2s(unsigned dst, unsigned src, unsigned bytes, unsigned mb) {
    asm volatile("cp.async.bulk.shared::cluster.shared::cta.mbarrier::complete_tx::bytes "
                 "[%0], [%1], %2, [%3];"
                 :: "r"(dst), "r"(src), "r"(bytes), "r"(mb) : "memory");
}
__device__ __forceinline__ void fence_proxy_async_cta() {
    asm volatile("fence.proxy.async.shared::cta;" ::: "memory");
}
__device__ __forceinline__ void mbar_init(unsigned mb, unsigned cnt) {
    asm volatile("mbarrier.init.shared.b64 [%0], %1;" :: "r"(mb), "r"(cnt) : "memory");
}
__device__ __forceinline__ void mbar_inval(unsigned mb) {
    asm volatile("mbarrier.inval.shared.b64 [%0];" :: "r"(mb) : "memory");
}
__device__ __forceinline__ void mbar_expect(unsigned mb, unsigned tx) {
    asm volatile("mbarrier.arrive.expect_tx.shared.b64 _, [%0], %1;" :: "r"(mb), "r"(tx) : "memory");
}
__device__ __forceinline__ void mbar_wait(unsigned addr, unsigned parity) {
    asm volatile(
        "{\n\t.reg .pred P;\n"
        "LW_%=:\n\t"
        "mbarrier.try_wait.parity.acquire.cluster.shared::cta.b64 P, [%0], %1;\n\t"
        "@P bra LD_%=;\n\t"
        "bra LW_%=;\n"
        "LD_%=:\n\t}"
        :: "r"(addr), "r"(parity) : "memory");
}
__device__ __forceinline__ uint pack2bf(float a, float b) {
    __nv_bfloat162 t = __floats2bfloat162_rn(a, b);
    return *(uint*)&t;
}
__device__ __forceinline__ float2 unpack2bf(uint v) {
    __nv_bfloat162 t = *(__nv_bfloat162*)&v;
    return __bfloat1622float2(t);
}
__device__ __forceinline__ void mma_bf16(float* d,
                                         uint a0, uint a1, uint a2, uint a3,
                                         uint b0, uint b1) {
    asm volatile("mma.sync.aligned.m16n8k16.row.col.f32.bf16.bf16.f32 "
                 "{%0,%1,%2,%3},{%4,%5,%6,%7},{%8,%9},{%0,%1,%2,%3};"
                 : "+f"(d[0]), "+f"(d[1]), "+f"(d[2]), "+f"(d[3])
                 : "r"(a0), "r"(a1), "r"(a2), "r"(a3), "r"(b0), "r"(b1));
}
__device__ __forceinline__ void ldsm_x4(uint& r0, uint& r1, uint& r2, uint& r3, unsigned a) {
    asm volatile("ldmatrix.sync.aligned.m8n8.x4.shared.b16 {%0,%1,%2,%3}, [%4];"
                 : "=r"(r0), "=r"(r1), "=r"(r2), "=r"(r3) : "r"(a));
}
__device__ __forceinline__ void ldsm_x4t(uint& r0, uint& r1, uint& r2, uint& r3, unsigned a) {
    asm volatile("ldmatrix.sync.aligned.m8n8.x4.trans.shared.b16 {%0,%1,%2,%3}, [%4];"
                 : "=r"(r0), "=r"(r1), "=r"(r2), "=r"(r3) : "r"(a));
}
__device__ __forceinline__ void cp_async16(unsigned saddr, const void* gaddr) {
    asm volatile("cp.async.cg.shared.global [%0], [%1], 16;" :: "r"(saddr), "l"(gaddr));
}
__device__ __forceinline__ float sigmoidf_(float z) {
    return 1.0f / (1.0f + __expf(-z));
}

// =====================================================================
// Fused gather + f32->bf16: Xbf[i,:] = bf16(emb[tokens[i],:])
// =====================================================================
__global__ __launch_bounds__(256) void gatherconv_kernel(
    const float* __restrict__ emb, const int* __restrict__ tokens,
    __nv_bfloat16* __restrict__ Xbf)
{
    int u = blockIdx.x * 256 + threadIdx.x;
    int row = u >> 5;
    int c4 = (u & 31) << 2;
    long tok = tokens[row];
    float4 v = *(const float4*)&emb[tok * En + c4];
    uint2 w;
    w.x = pack2bf(v.x, v.y);
    w.y = pack2bf(v.z, v.w);
    *(uint2*)&Xbf[(long)row * En + c4] = w;
}

// =====================================================================
// Prep: W1cat concat+convert (+bcat) and packed-U fragment tables for
// CLUSTER-4 layout: entry (which, r(0..3), w(0..7), kt(0..15), p(0..3), lane):
//   c = p*256 + r*64 + w*8 + grp ; k0 = kt*16 + tig*2
// =====================================================================
__global__ __launch_bounds__(256) void prep_kernel(
    const float* __restrict__ W1f, const float* __restrict__ W1b,
    const float* __restrict__ b1f, const float* __restrict__ b1b,
    const float* __restrict__ U1f, const float* __restrict__ U1b,
    const float* __restrict__ U2m,
    __nv_bfloat16* __restrict__ Wcat, float* __restrict__ bcat,
    uint2* __restrict__ Upk)
{
    int bid = blockIdx.x;
    if (bid < 256) {
        int u = bid * 256 + threadIdx.x;
        int row = u >> 9;
        int c4 = (u & 511) << 2;
        const float* src = (c4 < 1024) ? &W1f[row * 1024 + c4]
                                       : &W1b[row * 1024 + c4 - 1024];
        float4 v = *(const float4*)src;
        uint2 w;
        w.x = pack2bf(v.x, v.y);
        w.y = pack2bf(v.z, v.w);
        *(uint2*)&Wcat[(long)row * 2048 + c4] = w;
        if (bid == 0) {
            for (int j = threadIdx.x; j < 1024; j += 256) {
                bcat[j] = b1f[j];
                bcat[1024 + j] = b1b[j];
            }
        }
    } else {
        int g = (bid - 256) * 256 + threadIdx.x;   // 0 .. 196607
        int which = g >> 16;
        int idx = g & 65535;
        int lane = idx & 31;
        int rest = idx >> 5;                        // 0..2047
        int p  = rest & 3;
        int kt = (rest >> 2) & 15;
        int w  = (rest >> 6) & 7;
        int r  = (rest >> 9) & 3;
        const float* U = (which == 0) ? U1f : (which == 1) ? U1b : U2m;
        int tig = lane & 3, grp = lane >> 2;
        int c = p * 256 + r * 64 + w * 8 + grp;
        int k0 = kt * 16 + tig * 2;
        uint2 v;
        v.x = pack2bf(U[(long)(k0    ) * 1024 + c], U[(long)(k0 + 1) * 1024 + c]);
        v.y = pack2bf(U[(long)(k0 + 8) * 1024 + c], U[(long)(k0 + 9) * 1024 + c]);
        Upk[g] = v;
    }
}

// =====================================================================
// f32 -> bf16 conversion (vectorized, grid-stride). n % 4 == 0.
// =====================================================================
__global__ __launch_bounds__(256) void f2bf_kernel(
    const float* __restrict__ s, __nv_bfloat16* __restrict__ d, int n4)
{
    int i = blockIdx.x * blockDim.x + threadIdx.x;
    int stride = gridDim.x * blockDim.x;
    for (; i < n4; i += stride) {
        float4 v = ((const float4*)s)[i];
        uint2 w;
        w.x = pack2bf(v.x, v.y);
        w.y = pack2bf(v.z, v.w);
        ((uint2*)d)[i] = w;
    }
}

// =====================================================================
// bf16 GEMM v5 (unchanged): 2-stage cp.async pipeline + ldmatrix.
// =====================================================================
#define A_STG 18432
#define B_STG 17408
#define B_OFF 36864
#define GEMM_SMEM 71680

__global__ __launch_bounds__(256) void gemm_bf16_v5(
    const __nv_bfloat16* __restrict__ A, const __nv_bfloat16* __restrict__ B,
    const float* __restrict__ bias, void* __restrict__ C,
    int M, int N, int K, int lda, int obf)
{
    extern __shared__ char dynsm[];
    const unsigned sbase = (unsigned)__cvta_generic_to_shared(dynsm);

    const int bm = blockIdx.y * 128;
    const int bn = blockIdx.x * 128;
    const int tid = threadIdx.x;
    const int warp = tid >> 5, lane = tid & 31;
    const int wm = warp >> 2, wn = warp & 3;
    const int mBase = wm * 64, nBase = wn * 32;
    const int grp = lane >> 2, tig = lane & 3;

    auto stage = [&](int kb, int st) {
#pragma unroll
        for (int i = 0; i < 4; i++) {
            int idx = tid + i * 256;
            int row = idx >> 3, ch = idx & 7;
            unsigned off = (unsigned)(st * A_STG + row * 144 + ch * 16);
            if (bm + row < M) {
                cp_async16(sbase + off, A + (long)(bm + row) * lda + kb * 64 + ch * 8);
            } else {
                *(uint4*)(dynsm + off) = make_uint4(0, 0, 0, 0);
            }
        }
#pragma unroll
        for (int i = 0; i < 4; i++) {
            int idx = tid + i * 256;
            int k = idx >> 4, ch = idx & 15;
            int gc = bn + ch * 8;
            unsigned off = (unsigned)(B_OFF + st * B_STG + k * 272 + ch * 16);
            if (gc < N) {
                cp_async16(sbase + off, B + (long)(kb * 64 + k) * N + gc);
            } else {
                *(uint4*)(dynsm + off) = make_uint4(0, 0, 0, 0);
            }
        }
        asm volatile("cp.async.commit_group;");
    };

    float acc[4][4][4];
#pragma unroll
    for (int a = 0; a < 4; a++)
#pragma unroll
        for (int b = 0; b < 4; b++)
#pragma unroll
            for (int c = 0; c < 4; c++) acc[a][b][c] = 0.f;

    const int nk = K >> 6;
    stage(0, 0);

    for (int kb = 0; kb < nk; kb++) {
        int st = kb & 1;
        if (kb + 1 < nk) {
            stage(kb + 1, st ^ 1);
            asm volatile("cp.async.wait_group 1;");
        } else {
            asm volatile("cp.async.wait_group 0;");
        }
        __syncthreads();

        unsigned aRow = sbase + (unsigned)(st * A_STG)
                      + (unsigned)((mBase + (lane & 15)) * 144)
                      + (unsigned)((lane >> 4) << 4);
        unsigned bCol = sbase + (unsigned)(B_OFF + st * B_STG)
                      + (unsigned)((lane & 15) * 272)
                      + (unsigned)(nBase * 2 + ((lane >> 4) << 4));

#pragma unroll
        for (int kt = 0; kt < 4; kt++) {
            uint afr[4][4];
#pragma unroll
            for (int mi = 0; mi < 4; mi++)
                ldsm_x4(afr[mi][0], afr[mi][1], afr[mi][2], afr[mi][3],
                        aRow + (unsigned)(mi * 16 * 144 + kt * 32));
            uint bfr[2][4];
#pragma unroll
            for (int nh = 0; nh < 2; nh++)
                ldsm_x4t(bfr[nh][0], bfr[nh][1], bfr[nh][2], bfr[nh][3],
                         bCol + (unsigned)(kt * 16 * 272 + nh * 32));
#pragma unroll
            for (int nh = 0; nh < 2; nh++)
#pragma unroll
                for (int hf = 0; hf < 2; hf++) {
                    int ni = nh * 2 + hf;
                    uint b0 = bfr[nh][hf * 2], b1 = bfr[nh][hf * 2 + 1];
#pragma unroll
                    for (int mi = 0; mi < 4; mi++)
                        mma_bf16(acc[mi][ni], afr[mi][0], afr[mi][1], afr[mi][2], afr[mi][3], b0, b1);
                }
        }
        __syncthreads();
    }

#pragma unroll
    for (int mi = 0; mi < 4; mi++) {
#pragma unroll
        for (int ni = 0; ni < 4; ni++) {
            int r0 = bm + mBase + mi * 16 + grp;
            int c0 = bn + nBase + ni * 8 + tig * 2;
            float bv0 = (bias && c0     < N) ? bias[c0]     : 0.f;
            float bv1 = (bias && c0 + 1 < N) ? bias[c0 + 1] : 0.f;
            float o0 = acc[mi][ni][0] + bv0, o1 = acc[mi][ni][1] + bv1;
            float o2 = acc[mi][ni][2] + bv0, o3 = acc[mi][ni][3] + bv1;
            int r1 = r0 + 8;
            if (obf) {
                __nv_bfloat16* Cb = (__nv_bfloat16*)C;
                if (r0 < M && c0 + 1 < N)
                    *(uint*)&Cb[(long)r0 * N + c0] = pack2bf(o0, o1);
                if (r1 < M && c0 + 1 < N)
                    *(uint*)&Cb[(long)r1 * N + c0] = pack2bf(o2, o3);
            } else {
                float* Cf = (float*)C;
                if (r0 < M) {
                    if (c0     < N) Cf[(long)r0 * N + c0]     = o0;
                    if (c0 + 1 < N) Cf[(long)r0 * N + c0 + 1] = o1;
                }
                if (r1 < M) {
                    if (c0     < N) Cf[(long)r1 * N + c0]     = o2;
                    if (c0 + 1 < N) Cf[(long)r1 * N + c0 + 1] = o3;
                }
            }
        }
    }
}

// =====================================================================
// LSTM v10: round-12 step body, TWO interleaved sample groups per
// cluster. Group B's compute hides group A's exchange latency and
// vice versa. Per-group state: barriers (2 phases), hrecv, staging,
// parity, cell state, z prefetch. Cluster carries 2*BSUB samples.
// =====================================================================
template<int BSUB, bool WRITE_HS>
__device__ __forceinline__ void lstm_body_tc4g2(
    const __nv_bfloat16* __restrict__ Z, const uint2* __restrict__ Upk,
    void* __restrict__ OUT, int sbase, int dir, int zstride)
{
    constexpr int CHUNK = BSUB * 128;            // bytes per rank chunk
    constexpr int HR = 4 * CHUNK;                // receive buffer per (g,phase)
    constexpr unsigned TX = 3 * CHUNK;           // remote bytes per (g,phase)
    __shared__ __align__(16) char hrecv[4][HR];  // [g*2+ph][rank][sample][128B]
    __shared__ __align__(16) char stg[4][CHUNK]; // [g*2+ph][sample][128B]
    __shared__ __align__(16) uint zblk[4];
    __shared__ __align__(8) unsigned long long mbar[4];   // [g*2+ph]

    const int tid = threadIdx.x;
    const int warp = tid >> 5, lane = tid & 31;
    const int tig = lane & 3, grp = lane >> 2;
    const unsigned r = ctarank();

    // resident U fragments: BF[kt][gate][2] (128 regs), shared by both groups
    uint BF[16][4][2];
    {
        const uint2* up = Upk + (((int)r * 8 + warp) << 11) + lane;
#pragma unroll
        for (int kt = 0; kt < 16; kt++)
#pragma unroll
            for (int p = 0; p < 4; p++) {
                uint2 v = up[(kt * 4 + p) << 5];
                BF[kt][p][0] = v.x;
                BF[kt][p][1] = v.y;
            }
    }
    for (int i = tid; i < 4 * HR / 4; i += 256) ((uint*)&hrecv[0][0])[i] = 0;
    if (tid < 4) zblk[tid] = 0;

    const unsigned mb_s = (unsigned)__cvta_generic_to_shared(&mbar[0]);
    const unsigned hr_s = (unsigned)__cvta_generic_to_shared(&hrecv[0][0]);
    const unsigned sg_s = (unsigned)__cvta_generic_to_shared(&stg[0][0]);
    const unsigned zb_s = (unsigned)__cvta_generic_to_shared(&zblk[0]);
    if (tid == 0) {
#pragma unroll
        for (int q = 0; q < 4; q++) mbar_init(mb_s + q * 8, 1);
        // arm phases consumed at steps 1 and 2 for both groups
        mbar_expect(mb_s + 1 * 8, TX);   // g0 phase1
        mbar_expect(mb_s + 0 * 8, TX);   // g0 phase0
        mbar_expect(mb_s + 3 * 8, TX);   // g1 phase1
        mbar_expect(mb_s + 2 * 8, TX);   // g1 phase0
    }
    __syncthreads();
    cluster_sync_all();

    // courier targets: warp 0..2 -> ranks (r+1+warp)&3
    unsigned rdst = 0, rmb = 0;
    if (warp < 3) {
        unsigned tr = (r + 1 + (unsigned)warp) & 3;
        rdst = mapa_addr(hr_s, tr);
        rmb  = mapa_addr(mb_s, tr);
    }

    // ldsm row addressing (shared by groups; group picks its hrecv slab)
    const int s15 = lane & 15, hf = lane >> 4;
    const bool srow = s15 < BSUB;
    const unsigned rowoff = (unsigned)(s15 * 128);

    const unsigned so = (unsigned)(grp * 128 + (((warp ^ grp) & 7) << 4) + tig * 4);

    const bool valid = grp < BSUB;
    const int gcol = (int)r * 64 + warp * 8 + tig * 2;
    float cstA0 = 0.f, cstA1 = 0.f, cstB0 = 0.f, cstB1 = 0.f;
    const __nv_bfloat16* zrA = Z + (long)(sbase + grp) * Tn * zstride + gcol;
    const __nv_bfloat16* zrB = Z + (long)(sbase + BSUB + grp) * Tn * zstride + gcol;

    uint zinA[4], zinB[4];
    if (valid) {
        const __nv_bfloat16* za = zrA + (long)(dir ? Tn - 1 : 0) * zstride;
        const __nv_bfloat16* zb = zrB + (long)(dir ? Tn - 1 : 0) * zstride;
#pragma unroll
        for (int g = 0; g < 4; g++) {
            zinA[g] = *(const uint*)(za + (g << 8));
            zinB[g] = *(const uint*)(zb + (g << 8));
        }
    }

    int pA0 = 0, pA1 = 0, pB0 = 0, pB1 = 0;

    // one group step (round-12 body verbatim, group-indexed state)
    auto group_step = [&](int gq, float& cs0, float& cs1, uint* zin,
                          int& pp0, int& pp1,
                          const __nv_bfloat16* zr0, int srow_base,
                          int step, int cur, int nxt, int t) {
        if (step > 0) {
            mbar_wait(mb_s + (unsigned)((gq + cur) * 8),
                      (unsigned)(cur ? pp1 : pp0));
            if (cur) pp1 ^= 1; else pp0 ^= 1;
            if (tid == 0 && step + 2 < Tn)
                mbar_expect(mb_s + (unsigned)((gq + cur) * 8), TX);
        }

        float acc[2][4][4];
#pragma unroll
        for (int e = 0; e < 2; e++)
#pragma unroll
            for (int p = 0; p < 4; p++)
#pragma unroll
                for (int j = 0; j < 4; j++) acc[e][p][j] = 0.f;
        const unsigned hb_p = hr_s + (unsigned)((gq + cur) * HR);
#pragma unroll
        for (int kt = 0; kt < 16; kt++) {
            unsigned a = srow
                ? (hb_p + (unsigned)((kt >> 2) * CHUNK) + rowoff
                        + (unsigned)(((((kt & 3) << 1) + hf) ^ s15) << 4))
                : zb_s;
            uint x0, x1, x2, x3;
            ldsm_x4(x0, x1, x2, x3, a);
            const int e = kt & 1;
            mma_bf16(acc[e][0], x0, x1, x2, x3, BF[kt][0][0], BF[kt][0][1]);
            mma_bf16(acc[e][1], x0, x1, x2, x3, BF[kt][1][0], BF[kt][1][1]);
            mma_bf16(acc[e][2], x0, x1, x2, x3, BF[kt][2][0], BF[kt][2][1]);
            mma_bf16(acc[e][3], x0, x1, x2, x3, BF[kt][3][0], BF[kt][3][1]);
        }

        uint hv = 0;
        if (valid) {
            float2 z0 = unpack2bf(zin[0]);
            float2 z1 = unpack2bf(zin[1]);
            float2 z2 = unpack2bf(zin[2]);
            float2 z3 = unpack2bf(zin[3]);
            float zi0 = acc[0][0][0] + acc[1][0][0] + z0.x;
            float zi1 = acc[0][0][1] + acc[1][0][1] + z0.y;
            float zf0 = acc[0][1][0] + acc[1][1][0] + z1.x;
            float zf1 = acc[0][1][1] + acc[1][1][1] + z1.y;
            float zg0 = acc[0][2][0] + acc[1][2][0] + z2.x;
            float zg1 = acc[0][2][1] + acc[1][2][1] + z2.y;
            float zo0 = acc[0][3][0] + acc[1][3][0] + z3.x;
            float zo1 = acc[0][3][1] + acc[1][3][1] + z3.y;
            cs0 = sigmoidf_(zf0) * cs0 + sigmoidf_(zi0) * fmaxf(zg0, 0.f);
            cs1 = sigmoidf_(zf1) * cs1 + sigmoidf_(zi1) * fmaxf(zg1, 0.f);
            float h0 = sigmoidf_(zo0) * fmaxf(cs0, 0.f);
            float h1 = sigmoidf_(zo1) * fmaxf(cs1, 0.f);
            hv = pack2bf(h0, h1);

            if (WRITE_HS) {
                *(uint*)((__nv_bfloat16*)OUT +
                         ((long)(srow_base + grp) * Tn + t) * 512 + dir * 256 + gcol) = hv;
            } else if (step == Tn - 1) {
                float* o = (float*)OUT + (srow_base + grp) * 256 + gcol;
                o[0] = h0; o[1] = h1;
            }
        }

        if (step < Tn - 1) {
            if (valid) {
                asm volatile("st.shared.b32 [%0], %1;"
                             :: "r"(sg_s + (unsigned)((gq + nxt) * CHUNK) + so),
                                "r"(hv) : "memory");
                asm volatile("st.shared.b32 [%0], %1;"
                             :: "r"(hr_s + (unsigned)((gq + nxt) * HR + (int)r * CHUNK) + so),
                                "r"(hv) : "memory");
            }
            __syncthreads();
            if (warp < 3 && lane == 0) {
                fence_proxy_async_cta();
                bulk_s2s(rdst + (unsigned)((gq + nxt) * HR + (int)r * CHUNK),
                         sg_s + (unsigned)((gq + nxt) * CHUNK),
                         (unsigned)CHUNK,
                         rmb + (unsigned)((gq + nxt) * 8));
            }
        }
    };

    for (int step = 0; step < Tn; ++step) {
        const int cur = step & 1, nxt = cur ^ 1;
        const int t = dir ? (Tn - 1 - step) : step;

        // prefetch next step z for BOTH groups (issued before any wait)
        uint znA[4], znB[4];
        if (valid && step + 1 < Tn) {
            const long tn = (long)(dir ? Tn - 2 - step : step + 1) * zstride;
#pragma unroll
            for (int g = 0; g < 4; g++) {
                znA[g] = *(const uint*)(zrA + tn + (g << 8));
                znB[g] = *(const uint*)(zrB + tn + (g << 8));
            }
        }

        group_step(0, cstA0, cstA1, zinA, pA0, pA1, zrA, sbase,        step, cur, nxt, t);
        group_step(2, cstB0, cstB1, zinB, pB0, pB1, zrB, sbase + BSUB, step, cur, nxt, t);

#pragma unroll
        for (int g = 0; g < 4; g++) { zinA[g] = znA[g]; zinB[g] = znB[g]; }
    }
    cluster_sync_all();
    if (tid == 0) {
#pragma unroll
        for (int q = 0; q < 4; q++) mbar_inval(mb_s + q * 8);
    }
}

__global__ void __cluster_dims__(4, 1, 1) __launch_bounds__(256, 1)
lstm1_kernel(const __nv_bfloat16* __restrict__ Zcat, const uint2* __restrict__ Upk,
             __nv_bfloat16* __restrict__ HS)
{
    int cid = blockIdx.x >> 2;          // 0..15
    int dir = cid >> 3;                 // 0: fw (0..7), 1: bw (8..15)
    int cl  = cid & 7;
    lstm_body_tc4g2<4, true>(Zcat + dir * 1024, Upk + dir * 65536, HS, cl * 8, dir, 2048);
}

__global__ void __cluster_dims__(4, 1, 1) __launch_bounds__(256, 1)
lstm2_kernel(const __nv_bfloat16* __restrict__ Z, const uint2* __restrict__ Upk,
             float* __restrict__ HL)
{
    int cid = blockIdx.x >> 2;          // 0..7
    lstm_body_tc4g2<4, false>(Z, Upk + 2 * 65536, HL, cid * 8, 0, 1024);
}

// =====================================================================
// Dense head + softmax
// =====================================================================
__global__ __launch_bounds__(256) void dense3_kernel(
    const float* __restrict__ HL, const float* __restrict__ W3,
    const float* __restrict__ b3, __nv_bfloat16* __restrict__ D3bf)
{
    __shared__ float h[256];
    int s = blockIdx.x;
    h[threadIdx.x] = HL[s * 256 + threadIdx.x];
    __syncthreads();
    for (int j = threadIdx.x; j < U3n; j += 256) {
        float acc = b3[j];
#pragma unroll 8
        for (int k = 0; k < 256; k++) acc = fmaf(h[k], W3[k * U3n + j], acc);
        D3bf[s * U3n + j] = __float2bfloat16_rn(fmaxf(acc, 0.f));
    }
}

__global__ __launch_bounds__(256) void softmax_kernel(float* __restrict__ X)
{
    __shared__ float red[256];
    float* x = X + (long)blockIdx.x * U4n;
    int tid = threadIdx.x;

    float m = -1e30f;
    for (int j = tid; j < U4n; j += 256) m = fmaxf(m, x[j]);
    red[tid] = m; __syncthreads();
    for (int s = 128; s > 0; s >>= 1) {
        if (tid < s) red[tid] = fmaxf(red[tid], red[tid + s]);
        __syncthreads();
    }
    m = red[0]; __syncthreads();

    float sum = 0.f;
    for (int j = tid; j < U4n; j += 256) {
        float e = __expf(x[j] - m);
        x[j] = e;
        sum += e;
    }
    red[tid] = sum; __syncthreads();
    for (int s = 128; s > 0; s >>= 1) {
        if (tid < s) red[tid] += red[tid + s];
        __syncthreads();
    }
    float inv = 1.f / red[0];
    __syncthreads();
    for (int j = tid; j < U4n; j += 256) x[j] *= inv;
}

// =====================================================================
// launcher
// =====================================================================
extern "C" void kernel_launch(void* const* d_in, const int* in_sizes, int n_in,
                              void* d_out, int out_size)
{
    const int*   tokens = (const int*)  d_in[0];
    const float* emb    = (const float*)d_in[1];
    const float* W1f    = (const float*)d_in[2];
    const float* U1f    = (const float*)d_in[3];
    const float* b1f    = (const float*)d_in[4];
    const float* W1b    = (const float*)d_in[5];
    const float* U1b    = (const float*)d_in[6];
    const float* b1b    = (const float*)d_in[7];
    const float* W2     = (const float*)d_in[8];
    const float* U2m    = (const float*)d_in[9];
    const float* b2     = (const float*)d_in[10];
    const float* W3     = (const float*)d_in[11];
    const float* b3     = (const float*)d_in[12];
    const float* W4     = (const float*)d_in[13];
    const float* b4     = (const float*)d_in[14];
    float* out = (float*)d_out;

    float *HL, *bcat;
    __nv_bfloat16 *Z1cat, *Z2, *HS, *D3bf, *Xbf, *W1cat, *W2_bf, *W4_bf;
    uint2* Upk;
    cudaGetSymbolAddress((void**)&Z1cat, g_Z1cat);
    cudaGetSymbolAddress((void**)&Z2,    g_Z2);
    cudaGetSymbolAddress((void**)&HS,    g_HS);
    cudaGetSymbolAddress((void**)&HL,    g_HL);
    cudaGetSymbolAddress((void**)&D3bf,  g_D3bf);
    cudaGetSymbolAddress((void**)&Xbf,   g_Xbf);
    cudaGetSymbolAddress((void**)&W1cat, g_W1cat);
    cudaGetSymbolAddress((void**)&bcat,  g_bcat);
    cudaGetSymbolAddress((void**)&W2_bf, g_W2_bf);
    cudaGetSymbolAddress((void**)&W4_bf, g_W4_bf);
    cudaGetSymbolAddress((void**)&Upk,   g_Upk);

    cudaFuncSetAttribute((const void*)gemm_bf16_v5,
                         cudaFuncAttributeMaxDynamicSharedMemorySize, GEMM_SMEM);

    // 0: fused gather+convert of used embedding rows
    gatherconv_kernel<<<2048, 256>>>(emb, tokens, Xbf);
    // 1: all weight prep for LSTM1/LSTM2 (W1cat, bcat, packed U tables)
    prep_kernel<<<1024, 256>>>(W1f, W1b, b1f, b1b, U1f, U1b, U2m, W1cat, bcat, Upk);
    // 2: fused LSTM1 input projection (fw|bw), bf16 output
    {
        dim3 grid(16, 128);
        gemm_bf16_v5<<<grid, 256, GEMM_SMEM>>>(Xbf, W1cat, bcat, Z1cat,
                                               ROWS, 2048, En, En, 1);
    }
    // 3: BiLSTM layer 1  (profiled launch) — 16 clusters, 2 groups each
    lstm1_kernel<<<64, 256>>>(Z1cat, Upk, HS);
    // 4,5: head weight conversions (consumed at launches 6 and 9)
    f2bf_kernel<<<512,  256>>>(W2, W2_bf, 512 * 1024 / 4);
    f2bf_kernel<<<1024, 256>>>(W4, W4_bf, 512 * U4n / 4);
    // 6: LSTM2 input projection, bf16 output
    {
        dim3 grid(8, 128);
        gemm_bf16_v5<<<grid, 256, GEMM_SMEM>>>(HS, W2_bf, b2, Z2,
                                               ROWS, 1024, 512, 512, 1);
    }
    // 7: LSTM2 (h_last only) — 8 clusters, 2 groups each
    lstm2_kernel<<<32, 256>>>(Z2, Upk, HL);
    // 8: dense relu -> bf16
    dense3_kernel<<<Bn, 256>>>(HL, W3, b3, D3bf);
    // 9: logits GEMM into d_out (fp32 output)
    {
        dim3 grid((U4n + 127) / 128, 1);
        gemm_bf16_v5<<<grid, 256, GEMM_SMEM>>>(D3bf, W4_bf, b4, out,
                                               Bn, U4n, U3n, U3n, 0);
    }
    // 10: softmax in place
    softmax_kernel<<<Bn, 256>>>(out);
}

// round 16
// speedup vs baseline: 1.7590x; 1.7590x over previous
#include <cuda_runtime.h>
#include <cuda_bf16.h>
#include <cstdint>

typedef unsigned int uint;

// ---------------- problem constants ----------------
#define Bn   64
#define Tn   256
#define En   128
#define H1   256
#define H2   256
#define U3n  512
#define U4n  5000
#define ROWS (Bn*Tn)      // 16384

// ---------------- scratch ----------------
__device__ __nv_bfloat16 g_Z1cat[ROWS * 2048];    // bf16 (fw 0..1023, bw 1024..2047)
__device__ __nv_bfloat16 g_Z2 [ROWS * 1024];      // bf16
__device__ __nv_bfloat16 g_HS[ROWS * 512];
__device__ float g_HL [Bn * H2];
__device__ __nv_bfloat16 g_D3bf[Bn * U3n];
__device__ __nv_bfloat16 g_Xbf[ROWS * En];
__device__ __nv_bfloat16 g_W1cat[En * 2048];
__device__ float g_bcat[2048];
__device__ __nv_bfloat16 g_W2_bf [512 * 1024];
__device__ __nv_bfloat16 g_W4_bf [512 * U4n];
__device__ uint2 g_Upk[3 * 65536];                // packed U frags: U1f, U1b, U2m

// ---------------- helpers ----------------
__device__ __forceinline__ unsigned ctarank() {
    unsigned r; asm("mov.u32 %0, %%cluster_ctarank;" : "=r"(r)); return r;
}
__device__ __forceinline__ void cluster_sync_all() {
    asm volatile("barrier.cluster.arrive.aligned;\n\tbarrier.cluster.wait.aligned;" ::: "memory");
}
__device__ __forceinline__ unsigned mapa_addr(unsigned a, unsigned rank) {
    unsigned ra;
    asm volatile("mapa.shared::cluster.u32 %0, %1, %2;" : "=r"(ra) : "r"(a), "r"(rank));
    return ra;
}
__device__ __forceinline__ void bulk_s2s(unsigned dst, unsigned src, unsigned bytes, unsigned mb) {
    asm volatile("cp.async.bulk.shared::cluster.shared::cta.mbarrier::complete_tx::bytes "
                 "[%0], [%1], %2, [%3];"
                 :: "r"(dst), "r"(src), "r"(bytes), "r"(mb) : "memory");
}
__device__ __forceinline__ void fence_proxy_async_cta() {
    asm volatile("fence.proxy.async.shared::cta;" ::: "memory");
}
__device__ __forceinline__ void mbar_init(unsigned mb, unsigned cnt) {
    asm volatile("mbarrier.init.shared.b64 [%0], %1;" :: "r"(mb), "r"(cnt) : "memory");
}
__device__ __forceinline__ void mbar_inval(unsigned mb) {
    asm volatile("mbarrier.inval.shared.b64 [%0];" :: "r"(mb) : "memory");
}
__device__ __forceinline__ void mbar_expect(unsigned mb, unsigned tx) {
    asm volatile("mbarrier.arrive.expect_tx.shared.b64 _, [%0], %1;" :: "r"(mb), "r"(tx) : "memory");
}
__device__ __forceinline__ void mbar_wait(unsigned addr, unsigned parity) {
    asm volatile(
        "{\n\t.reg .pred P;\n"
        "LW_%=:\n\t"
        "mbarrier.try_wait.parity.acquire.cluster.shared::cta.b64 P, [%0], %1;\n\t"
        "@P bra LD_%=;\n\t"
        "bra LW_%=;\n"
        "LD_%=:\n\t}"
        :: "r"(addr), "r"(parity) : "memory");
}
__device__ __forceinline__ uint pack2bf(float a, float b) {
    __nv_bfloat162 t = __floats2bfloat162_rn(a, b);
    return *(uint*)&t;
}
__device__ __forceinline__ float2 unpack2bf(uint v) {
    __nv_bfloat162 t = *(__nv_bfloat162*)&v;
    return __bfloat1622float2(t);
}
__device__ __forceinline__ void mma_bf16(float* d,
                                         uint a0, uint a1, uint a2, uint a3,
                                         uint b0, uint b1) {
    asm volatile("mma.sync.aligned.m16n8k16.row.col.f32.bf16.bf16.f32 "
                 "{%0,%1,%2,%3},{%4,%5,%6,%7},{%8,%9},{%0,%1,%2,%3};"
                 : "+f"(d[0]), "+f"(d[1]), "+f"(d[2]), "+f"(d[3])
                 : "r"(a0), "r"(a1), "r"(a2), "r"(a3), "r"(b0), "r"(b1));
}
__device__ __forceinline__ void ldsm_x4(uint& r0, uint& r1, uint& r2, uint& r3, unsigned a) {
    asm volatile("ldmatrix.sync.aligned.m8n8.x4.shared.b16 {%0,%1,%2,%3}, [%4];"
                 : "=r"(r0), "=r"(r1), "=r"(r2), "=r"(r3) : "r"(a));
}
__device__ __forceinline__ void ldsm_x4t(uint& r0, uint& r1, uint& r2, uint& r3, unsigned a) {
    asm volatile("ldmatrix.sync.aligned.m8n8.x4.trans.shared.b16 {%0,%1,%2,%3}, [%4];"
                 : "=r"(r0), "=r"(r1), "=r"(r2), "=r"(r3) : "r"(a));
}
__device__ __forceinline__ void cp_async16(unsigned saddr, const void* gaddr) {
    asm volatile("cp.async.cg.shared.global [%0], [%1], 16;" :: "r"(saddr), "l"(gaddr));
}
__device__ __forceinline__ float sigmoidf_(float z) {
    return 1.0f / (1.0f + __expf(-z));
}

// =====================================================================
// prepall: gatherconv (bid<2048) + W1cat/bcat (bid<2304) + Upk tables.
// grid = 3072 x 256.
// =====================================================================
__global__ __launch_bounds__(256) void prepall_kernel(
    const float* __restrict__ emb, const int* __restrict__ tokens,
    __nv_bfloat16* __restrict__ Xbf,
    const float* __restrict__ W1f, const float* __restrict__ W1b,
    const float* __restrict__ b1f, const float* __restrict__ b1b,
    const float* __restrict__ U1f, const float* __restrict__ U1b,
    const float* __restrict__ U2m,
    __nv_bfloat16* __restrict__ Wcat, float* __restrict__ bcat,
    uint2* __restrict__ Upk)
{
    int bid = blockIdx.x;
    if (bid < 2048) {
        // gather + convert embedding rows
        int u = bid * 256 + threadIdx.x;
        int row = u >> 5;
        int c4 = (u & 31) << 2;
        long tok = tokens[row];
        float4 v = *(const float4*)&emb[tok * En + c4];
        uint2 w;
        w.x = pack2bf(v.x, v.y);
        w.y = pack2bf(v.z, v.w);
        *(uint2*)&Xbf[(long)row * En + c4] = w;
    } else if (bid < 2304) {
        int u = (bid - 2048) * 256 + threadIdx.x;
        int row = u >> 9;
        int c4 = (u & 511) << 2;
        const float* src = (c4 < 1024) ? &W1f[row * 1024 + c4]
                                       : &W1b[row * 1024 + c4 - 1024];
        float4 v = *(const float4*)src;
        uint2 w;
        w.x = pack2bf(v.x, v.y);
        w.y = pack2bf(v.z, v.w);
        *(uint2*)&Wcat[(long)row * 2048 + c4] = w;
        if (bid == 2048) {
            for (int j = threadIdx.x; j < 1024; j += 256) {
                bcat[j] = b1f[j];
                bcat[1024 + j] = b1b[j];
            }
        }
    } else {
        int g = (bid - 2304) * 256 + threadIdx.x;   // 0 .. 196607
        int which = g >> 16;
        int idx = g & 65535;
        int lane = idx & 31;
        int rest = idx >> 5;                        // 0..2047
        int p  = rest & 3;
        int kt = (rest >> 2) & 15;
        int w  = (rest >> 6) & 7;
        int r  = (rest >> 9) & 3;
        const float* U = (which == 0) ? U1f : (which == 1) ? U1b : U2m;
        int tig = lane & 3, grp = lane >> 2;
        int c = p * 256 + r * 64 + w * 8 + grp;
        int k0 = kt * 16 + tig * 2;
        uint2 v;
        v.x = pack2bf(U[(long)(k0    ) * 1024 + c], U[(long)(k0 + 1) * 1024 + c]);
        v.y = pack2bf(U[(long)(k0 + 8) * 1024 + c], U[(long)(k0 + 9) * 1024 + c]);
        Upk[g] = v;
    }
}

// =====================================================================
// f2bf2: converts W2 (512*1024) then W4 (512*5000) in ONE launch.
// grid-stride over combined element range / 4.
// =====================================================================
__global__ __launch_bounds__(256) void f2bf2_kernel(
    const float* __restrict__ s1, __nv_bfloat16* __restrict__ d1, int n41,
    const float* __restrict__ s2, __nv_bfloat16* __restrict__ d2, int n42)
{
    int i = blockIdx.x * blockDim.x + threadIdx.x;
    int stride = gridDim.x * blockDim.x;
    int ntot = n41 + n42;
    for (; i < ntot; i += stride) {
        const float4* sp;
        uint2* dp;
        if (i < n41) { sp = (const float4*)s1 + i; dp = (uint2*)d1 + i; }
        else         { sp = (const float4*)s2 + (i - n41); dp = (uint2*)d2 + (i - n41); }
        float4 v = *sp;
        uint2 w;
        w.x = pack2bf(v.x, v.y);
        w.y = pack2bf(v.z, v.w);
        *dp = w;
    }
}

// =====================================================================
// bf16 GEMM v4 (round-12 exact): 3-stage cp.async pipeline + ldmatrix;
// output fp32 or bf16.
// =====================================================================
#define A_STG 18432
#define B_STG 17408
#define B_OFF 55296
#define GEMM_SMEM 107520

__global__ __launch_bounds__(256) void gemm_bf16_v4(
    const __nv_bfloat16* __restrict__ A, const __nv_bfloat16* __restrict__ B,
    const float* __restrict__ bias, void* __restrict__ C,
    int M, int N, int K, int lda, int obf)
{
    extern __shared__ char dynsm[];
    const unsigned sbase = (unsigned)__cvta_generic_to_shared(dynsm);

    const int bm = blockIdx.y * 128;
    const int bn = blockIdx.x * 128;
    const int tid = threadIdx.x;
    const int warp = tid >> 5, lane = tid & 31;
    const int wm = warp >> 2, wn = warp & 3;
    const int mBase = wm * 64, nBase = wn * 32;
    const int grp = lane >> 2, tig = lane & 3;

    auto stage = [&](int kb, int st) {
#pragma unroll
        for (int i = 0; i < 4; i++) {
            int idx = tid + i * 256;
            int row = idx >> 3, ch = idx & 7;
            unsigned off = (unsigned)(st * A_STG + row * 144 + ch * 16);
            if (bm + row < M) {
                cp_async16(sbase + off, A + (long)(bm + row) * lda + kb * 64 + ch * 8);
            } else {
                *(uint4*)(dynsm + off) = make_uint4(0, 0, 0, 0);
            }
        }
#pragma unroll
        for (int i = 0; i < 4; i++) {
            int idx = tid + i * 256;
            int k = idx >> 4, ch = idx & 15;
            int gc = bn + ch * 8;
            unsigned off = (unsigned)(B_OFF + st * B_STG + k * 272 + ch * 16);
            if (gc < N) {
                cp_async16(sbase + off, B + (long)(kb * 64 + k) * N + gc);
            } else {
                *(uint4*)(dynsm + off) = make_uint4(0, 0, 0, 0);
            }
        }
        asm volatile("cp.async.commit_group;");
    };

    float acc[4][4][4];
#pragma unroll
    for (int a = 0; a < 4; a++)
#pragma unroll
        for (int b = 0; b < 4; b++)
#pragma unroll
            for (int c = 0; c < 4; c++) acc[a][b][c] = 0.f;

    const int nk = K >> 6;
    stage(0, 0);
    if (nk > 1) stage(1, 1);

    for (int kb = 0; kb < nk; kb++) {
        int st = kb % 3;
        if (kb + 2 < nk) {
            stage(kb + 2, (kb + 2) % 3);
            asm volatile("cp.async.wait_group 2;");
        } else if (kb + 1 < nk) {
            asm volatile("cp.async.wait_group 1;");
        } else {
            asm volatile("cp.async.wait_group 0;");
        }
        __syncthreads();

        unsigned aRow = sbase + (unsigned)(st * A_STG)
                      + (unsigned)((mBase + (lane & 15)) * 144)
                      + (unsigned)((lane >> 4) << 4);
        unsigned bCol = sbase + (unsigned)(B_OFF + st * B_STG)
                      + (unsigned)((lane & 15) * 272)
                      + (unsigned)(nBase * 2 + ((lane >> 4) << 4));

#pragma unroll
        for (int kt = 0; kt < 4; kt++) {
            uint afr[4][4];
#pragma unroll
            for (int mi = 0; mi < 4; mi++)
                ldsm_x4(afr[mi][0], afr[mi][1], afr[mi][2], afr[mi][3],
                        aRow + (unsigned)(mi * 16 * 144 + kt * 32));
            uint bfr[2][4];
#pragma unroll
            for (int nh = 0; nh < 2; nh++)
                ldsm_x4t(bfr[nh][0], bfr[nh][1], bfr[nh][2], bfr[nh][3],
                         bCol + (unsigned)(kt * 16 * 272 + nh * 32));
#pragma unroll
            for (int nh = 0; nh < 2; nh++)
#pragma unroll
                for (int hf = 0; hf < 2; hf++) {
                    int ni = nh * 2 + hf;
                    uint b0 = bfr[nh][hf * 2], b1 = bfr[nh][hf * 2 + 1];
#pragma unroll
                    for (int mi = 0; mi < 4; mi++)
                        mma_bf16(acc[mi][ni], afr[mi][0], afr[mi][1], afr[mi][2], afr[mi][3], b0, b1);
                }
        }
        __syncthreads();
    }

#pragma unroll
    for (int mi = 0; mi < 4; mi++) {
#pragma unroll
        for (int ni = 0; ni < 4; ni++) {
            int r0 = bm + mBase + mi * 16 + grp;
            int c0 = bn + nBase + ni * 8 + tig * 2;
            float bv0 = (bias && c0     < N) ? bias[c0]     : 0.f;
            float bv1 = (bias && c0 + 1 < N) ? bias[c0 + 1] : 0.f;
            float o0 = acc[mi][ni][0] + bv0, o1 = acc[mi][ni][1] + bv1;
            float o2 = acc[mi][ni][2] + bv0, o3 = acc[mi][ni][3] + bv1;
            int r1 = r0 + 8;
            if (obf) {
                __nv_bfloat16* Cb = (__nv_bfloat16*)C;
                if (r0 < M && c0 + 1 < N)
                    *(uint*)&Cb[(long)r0 * N + c0] = pack2bf(o0, o1);
                if (r1 < M && c0 + 1 < N)
                    *(uint*)&Cb[(long)r1 * N + c0] = pack2bf(o2, o3);
            } else {
                float* Cf = (float*)C;
                if (r0 < M) {
                    if (c0     < N) Cf[(long)r0 * N + c0]     = o0;
                    if (c0 + 1 < N) Cf[(long)r0 * N + c0 + 1] = o1;
                }
                if (r1 < M) {
                    if (c0     < N) Cf[(long)r1 * N + c0]     = o2;
                    if (c0 + 1 < N) Cf[(long)r1 * N + c0 + 1] = o3;
                }
            }
        }
    }
}

// =====================================================================
// LSTM (round-12 body, verbatim): cluster-4, gate-natural tiles,
// staging buffer + 3 bulk copies, bf16 Z input. CHANGE-FROZEN.
// =====================================================================
template<int BSUB, bool WRITE_HS>
__device__ __forceinline__ void lstm_body_tc4(
    const __nv_bfloat16* __restrict__ Z, const uint2* __restrict__ Upk,
    void* __restrict__ OUT, int sbase, int dir, int zstride)
{
    constexpr int CHUNK = BSUB * 128;            // bytes per rank chunk
    constexpr int HR = 4 * CHUNK;                // receive buffer per phase
    constexpr unsigned TX = 3 * CHUNK;           // remote bytes per phase
    __shared__ __align__(16) char hrecv[2][HR];  // [par][rank][sample][128B]
    __shared__ __align__(16) char stg[2][CHUNK]; // [par][sample][128B] permuted
    __shared__ __align__(16) uint zblk[4];
    __shared__ __align__(8) unsigned long long mbar[2];

    const int tid = threadIdx.x;
    const int warp = tid >> 5, lane = tid & 31;
    const int tig = lane & 3, grp = lane >> 2;
    const unsigned r = ctarank();

    // resident U fragments: BF[kt][gate][2] (128 regs)
    uint BF[16][4][2];
    {
        const uint2* up = Upk + (((int)r * 8 + warp) << 11) + lane;
#pragma unroll
        for (int kt = 0; kt < 16; kt++)
#pragma unroll
            for (int p = 0; p < 4; p++) {
                uint2 v = up[(kt * 4 + p) << 5];
                BF[kt][p][0] = v.x;
                BF[kt][p][1] = v.y;
            }
    }
    for (int i = tid; i < HR / 4; i += 256) ((uint*)&hrecv[0][0])[i] = 0;
    if (tid < 4) zblk[tid] = 0;

    const unsigned mb_s = (unsigned)__cvta_generic_to_shared(&mbar[0]);
    const unsigned hr_s = (unsigned)__cvta_generic_to_shared(&hrecv[0][0]);
    const unsigned sg_s = (unsigned)__cvta_generic_to_shared(&stg[0][0]);
    const unsigned zb_s = (unsigned)__cvta_generic_to_shared(&zblk[0]);
    if (tid == 0) {
        mbar_init(mb_s, 1);
        mbar_init(mb_s + 8, 1);
        mbar_expect(mb_s + 8, TX);   // phase fed by step-0 sends
        mbar_expect(mb_s,     TX);   // phase fed by step-1 sends
    }
    __syncthreads();
    cluster_sync_all();

    // courier targets: warp 0..2 -> ranks (r+1+warp)&3
    unsigned rdst = 0, rmb = 0;
    if (warp < 3) {
        unsigned tr = (r + 1 + (unsigned)warp) & 3;
        rdst = mapa_addr(hr_s, tr);
        rmb  = mapa_addr(mb_s, tr);
    }

    // ldsm row addressing: row s15 -> rank chunk by kt, permuted 16B chunk
    const int s15 = lane & 15, hf = lane >> 4;
    const bool srow = s15 < BSUB;
    const unsigned rowoff = (unsigned)(s15 * 128);

    // staging/local write offset (each valid lane stores its packed pair)
    const unsigned so = (unsigned)(grp * 128 + (((warp ^ grp) & 7) << 4) + tig * 4);

    const bool valid = grp < BSUB;
    const int gcol = (int)r * 64 + warp * 8 + tig * 2;   // global unit (even)
    float cst0 = 0.f, cst1 = 0.f;
    const __nv_bfloat16* zr0 = Z + (long)(sbase + grp) * Tn * zstride + gcol;

    uint zin[4], zn1[4];
    if (valid) {
        const __nv_bfloat16* za = zr0 + (long)(dir ? Tn - 1 : 0) * zstride;
        const __nv_bfloat16* zb = zr0 + (long)(dir ? Tn - 2 : 1) * zstride;
#pragma unroll
        for (int g = 0; g < 4; g++) {
            zin[g] = *(const uint*)(za + (g << 8));
            zn1[g] = *(const uint*)(zb + (g << 8));
        }
    }

    int par0 = 0, par1 = 0;
    for (int step = 0; step < Tn; ++step) {
        const int cur = step & 1, nxt = cur ^ 1;
        const int t = dir ? (Tn - 1 - step) : step;

        uint zn2[4];
        if (valid && step + 2 < Tn) {
            const __nv_bfloat16* zr = zr0 + (long)(dir ? Tn - 3 - step : step + 2) * zstride;
#pragma unroll
            for (int g = 0; g < 4; g++) zn2[g] = *(const uint*)(zr + (g << 8));
        }

        if (step > 0) {
            mbar_wait(mb_s + cur * 8, (unsigned)(cur ? par1 : par0));
            if (cur) par1 ^= 1; else par0 ^= 1;
            if (tid == 0 && step + 2 < Tn) mbar_expect(mb_s + cur * 8, TX);
        }

        // ---- z = h @ U : 8 chains (2 per gate), no transpose needed ----
        float acc[2][4][4];
#pragma unroll
        for (int e = 0; e < 2; e++)
#pragma unroll
            for (int p = 0; p < 4; p++)
#pragma unroll
                for (int j = 0; j < 4; j++) acc[e][p][j] = 0.f;
        const unsigned hb_p = hr_s + (unsigned)(cur * HR);
#pragma unroll
        for (int kt = 0; kt < 16; kt++) {
            unsigned a = srow
                ? (hb_p + (unsigned)((kt >> 2) * CHUNK) + rowoff
                        + (unsigned)(((((kt & 3) << 1) + hf) ^ s15) << 4))
                : zb_s;
            uint x0, x1, x2, x3;
            ldsm_x4(x0, x1, x2, x3, a);
            const int e = kt & 1;
            mma_bf16(acc[e][0], x0, x1, x2, x3, BF[kt][0][0], BF[kt][0][1]);
            mma_bf16(acc[e][1], x0, x1, x2, x3, BF[kt][1][0], BF[kt][1][1]);
            mma_bf16(acc[e][2], x0, x1, x2, x3, BF[kt][2][0], BF[kt][2][1]);
            mma_bf16(acc[e][3], x0, x1, x2, x3, BF[kt][3][0], BF[kt][3][1]);
        }

        // ---- cell update (2 units per lane, gates in-register) ----
        uint hv = 0;
        if (valid) {
            float2 z0 = unpack2bf(zin[0]);
            float2 z1 = unpack2bf(zin[1]);
            float2 z2 = unpack2bf(zin[2]);
            float2 z3 = unpack2bf(zin[3]);
            float zi0 = acc[0][0][0] + acc[1][0][0] + z0.x;
            float zi1 = acc[0][0][1] + acc[1][0][1] + z0.y;
            float zf0 = acc[0][1][0] + acc[1][1][0] + z1.x;
            float zf1 = acc[0][1][1] + acc[1][1][1] + z1.y;
            float zg0 = acc[0][2][0] + acc[1][2][0] + z2.x;
            float zg1 = acc[0][2][1] + acc[1][2][1] + z2.y;
            float zo0 = acc[0][3][0] + acc[1][3][0] + z3.x;
            float zo1 = acc[0][3][1] + acc[1][3][1] + z3.y;
            cst0 = sigmoidf_(zf0) * cst0 + sigmoidf_(zi0) * fmaxf(zg0, 0.f);
            cst1 = sigmoidf_(zf1) * cst1 + sigmoidf_(zi1) * fmaxf(zg1, 0.f);
            float h0 = sigmoidf_(zo0) * fmaxf(cst0, 0.f);
            float h1 = sigmoidf_(zo1) * fmaxf(cst1, 0.f);
            hv = pack2bf(h0, h1);

            if (WRITE_HS) {
                *(uint*)((__nv_bfloat16*)OUT +
                         ((long)(sbase + grp) * Tn + t) * 512 + dir * 256 + gcol) = hv;
            } else if (step == Tn - 1) {
                float* o = (float*)OUT + (sbase + grp) * 256 + gcol;
                o[0] = h0; o[1] = h1;
            }
        }

        // ---- exchange: local self chunk + 3 remote bulk copies ----
        if (step < Tn - 1) {
            if (valid) {
                asm volatile("st.shared.b32 [%0], %1;"
                             :: "r"(sg_s + (unsigned)(nxt * CHUNK) + so), "r"(hv) : "memory");
                asm volatile("st.shared.b32 [%0], %1;"
                             :: "r"(hr_s + (unsigned)(nxt * HR + (int)r * CHUNK) + so),
                                "r"(hv) : "memory");
            }
            __syncthreads();
            if (warp < 3 && lane == 0) {
                fence_proxy_async_cta();
                bulk_s2s(rdst + (unsigned)(nxt * HR + (int)r * CHUNK),
                         sg_s + (unsigned)(nxt * CHUNK),
                         (unsigned)CHUNK,
                         rmb + (unsigned)(nxt * 8));
            }
        }
#pragma unroll
        for (int g = 0; g < 4; g++) { zin[g] = zn1[g]; zn1[g] = zn2[g]; }
    }
    cluster_sync_all();
    if (tid == 0) { mbar_inval(mb_s); mbar_inval(mb_s + 8); }
}

__global__ void __cluster_dims__(4, 1, 1) __launch_bounds__(256, 1)
lstm1_kernel(const __nv_bfloat16* __restrict__ Zcat, const uint2* __restrict__ Upk,
             __nv_bfloat16* __restrict__ HS)
{
    int cid = blockIdx.x >> 2;          // 0..31
    int dir = cid >> 4;                 // 0: fw (0..15), 1: bw (16..31)
    int cl  = cid & 15;
    lstm_body_tc4<4, true>(Zcat + dir * 1024, Upk + dir * 65536, HS, cl * 4, dir, 2048);
}

__global__ void __cluster_dims__(4, 1, 1) __launch_bounds__(256, 1)
lstm2_kernel(const __nv_bfloat16* __restrict__ Z, const uint2* __restrict__ Upk,
             float* __restrict__ HL)
{
    int cid = blockIdx.x >> 2;          // 0..31
    lstm_body_tc4<2, false>(Z, Upk + 2 * 65536, HL, cid * 2, 0, 1024);
}

// =====================================================================
// Dense head + softmax
// =====================================================================
__global__ __launch_bounds__(256) void dense3_kernel(
    const float* __restrict__ HL, const float* __restrict__ W3,
    const float* __restrict__ b3, __nv_bfloat16* __restrict__ D3bf)
{
    __shared__ float h[256];
    int s = blockIdx.x;
    h[threadIdx.x] = HL[s * 256 + threadIdx.x];
    __syncthreads();
    for (int j = threadIdx.x; j < U3n; j += 256) {
        float acc = b3[j];
#pragma unroll 8
        for (int k = 0; k < 256; k++) acc = fmaf(h[k], W3[k * U3n + j], acc);
        D3bf[s * U3n + j] = __float2bfloat16_rn(fmaxf(acc, 0.f));
    }
}

__global__ __launch_bounds__(256) void softmax_kernel(float* __restrict__ X)
{
    __shared__ float red[256];
    float* x = X + (long)blockIdx.x * U4n;
    int tid = threadIdx.x;

    float m = -1e30f;
    for (int j = tid; j < U4n; j += 256) m = fmaxf(m, x[j]);
    red[tid] = m; __syncthreads();
    for (int s = 128; s > 0; s >>= 1) {
        if (tid < s) red[tid] = fmaxf(red[tid], red[tid + s]);
        __syncthreads();
    }
    m = red[0]; __syncthreads();

    float sum = 0.f;
    for (int j = tid; j < U4n; j += 256) {
        float e = __expf(x[j] - m);
        x[j] = e;
        sum += e;
    }
    red[tid] = sum; __syncthreads();
    for (int s = 128; s > 0; s >>= 1) {
        if (tid < s) red[tid] += red[tid + s];
        __syncthreads();
    }
    float inv = 1.f / red[0];
    __syncthreads();
    for (int j = tid; j < U4n; j += 256) x[j] *= inv;
}

// =====================================================================
// launcher — order arranged so ncu (-s 5) profiles lstm2_kernel:
// 0 prepall, 1 f2bf2, 2 gemm1, 3 lstm1, 4 gemm2, 5 lstm2, 6 dense3,
// 7 logits, 8 softmax.
// =====================================================================
extern "C" void kernel_launch(void* const* d_in, const int* in_sizes, int n_in,
                              void* d_out, int out_size)
{
    const int*   tokens = (const int*)  d_in[0];
    const float* emb    = (const float*)d_in[1];
    const float* W1f    = (const float*)d_in[2];
    const float* U1f    = (const float*)d_in[3];
    const float* b1f    = (const float*)d_in[4];
    const float* W1b    = (const float*)d_in[5];
    const float* U1b    = (const float*)d_in[6];
    const float* b1b    = (const float*)d_in[7];
    const float* W2     = (const float*)d_in[8];
    const float* U2m    = (const float*)d_in[9];
    const float* b2     = (const float*)d_in[10];
    const float* W3     = (const float*)d_in[11];
    const float* b3     = (const float*)d_in[12];
    const float* W4     = (const float*)d_in[13];
    const float* b4     = (const float*)d_in[14];
    float* out = (float*)d_out;

    float *HL, *bcat;
    __nv_bfloat16 *Z1cat, *Z2, *HS, *D3bf, *Xbf, *W1cat, *W2_bf, *W4_bf;
    uint2* Upk;
    cudaGetSymbolAddress((void**)&Z1cat, g_Z1cat);
    cudaGetSymbolAddress((void**)&Z2,    g_Z2);
    cudaGetSymbolAddress((void**)&HS,    g_HS);
    cudaGetSymbolAddress((void**)&HL,    g_HL);
    cudaGetSymbolAddress((void**)&D3bf,  g_D3bf);
    cudaGetSymbolAddress((void**)&Xbf,   g_Xbf);
    cudaGetSymbolAddress((void**)&W1cat, g_W1cat);
    cudaGetSymbolAddress((void**)&bcat,  g_bcat);
    cudaGetSymbolAddress((void**)&W2_bf, g_W2_bf);
    cudaGetSymbolAddress((void**)&W4_bf, g_W4_bf);
    cudaGetSymbolAddress((void**)&Upk,   g_Upk);

    cudaFuncSetAttribute((const void*)gemm_bf16_v4,
                         cudaFuncAttributeMaxDynamicSharedMemorySize, GEMM_SMEM);

    // 0: all prep (gather+convert emb, W1cat, bcat, Upk tables)
    prepall_kernel<<<3072, 256>>>(emb, tokens, Xbf,
                                  W1f, W1b, b1f, b1b, U1f, U1b, U2m,
                                  W1cat, bcat, Upk);
    // 1: head weight conversions (W2 + W4) in one launch
    f2bf2_kernel<<<1024, 256>>>(W2, W2_bf, 512 * 1024 / 4,
                                W4, W4_bf, 512 * U4n / 4);
    // 2: fused LSTM1 input projection (fw|bw), bf16 output
    {
        dim3 grid(16, 128);
        gemm_bf16_v4<<<grid, 256, GEMM_SMEM>>>(Xbf, W1cat, bcat, Z1cat,
                                               ROWS, 2048, En, En, 1);
    }
    // 3: BiLSTM layer 1
    lstm1_kernel<<<128, 256>>>(Z1cat, Upk, HS);
    // 4: LSTM2 input projection, bf16 output
    {
        dim3 grid(8, 128);
        gemm_bf16_v4<<<grid, 256, GEMM_SMEM>>>(HS, W2_bf, b2, Z2,
                                               ROWS, 1024, 512, 512, 1);
    }
    // 5: LSTM2 (h_last only)  — profiled launch (ncu -s 5 -c 1)
    lstm2_kernel<<<128, 256>>>(Z2, Upk, HL);
    // 6: dense relu -> bf16
    dense3_kernel<<<Bn, 256>>>(HL, W3, b3, D3bf);
    // 7: logits GEMM into d_out (fp32 output)
    {
        dim3 grid((U4n + 127) / 128, 1);
        gemm_bf16_v4<<<grid, 256, GEMM_SMEM>>>(D3bf, W4_bf, b4, out,
                                               Bn, U4n, U3n, U3n, 0);
    }
    // 8: softmax in place
    softmax_kernel<<<Bn, 256>>>(out);
}